// round 8
// baseline (speedup 1.0000x reference)
#include <cuda_runtime.h>
#include <math.h>

// Hausdorff, D=H=W=20, V=8000, batch 2. Exact integer squared-EDT.
// ONE kernel, block = (transform t, z-plane z0), no cross-block data deps.
// Each thread (x,y) builds its row's 20-bit z-occupancy from gmem, z-pass in
// O(1) (clz/ffs), y- and x-passes in SMEM. Tail: two-level arrival tree
// (per-transform counter -> 4-way global counter); last finalizes + resets.

#define INF_S 32000   // squared-distance "infinity" (max legit = 3*19^2 = 1083)
#define PAD   8

__device__ unsigned g_gmax[4 * PAD];   // per-transform max d2+1 (0 = none); zero-init
__device__ unsigned g_any[2 * PAD];    // any(mask A) per sample; zero-init
__device__ unsigned g_cnt[4 * PAD];    // per-transform arrival counters; zero-init
__device__ unsigned g_done = 0;        // transform-completion counter

__global__ void __launch_bounds__(416, 1)
haus_plane(const float* __restrict__ predict,
           const float* __restrict__ targetp,
           float* __restrict__ out)
{
    __shared__ int F1[400];   // z-pass result for plane z0, index x*20+y
    __shared__ int F2[400];   // y-pass result
    __shared__ int sred;
    __shared__ int sany;

    const int b  = blockIdx.x;       // t*20 + z0
    const int t  = b / 20, z0 = b - t * 20;
    const int n  = t >> 1,  m  = t & 1;
    const float* setSrc = (m ? targetp : predict) + n * 8000;
    const float* othSrc = (m ? predict : targetp) + n * 8000;
    const int tid = threadIdx.x;

    if (tid == 0) { sred = 0; sany = 0; }

    int x = 0, y = 0, oo = 0;
    unsigned rowbits = 0;
    if (tid < 400) {
        x = tid / 20; y = tid - x * 20;
        // Own (x,y) row over z: 20 contiguous floats = 5 x float4 (MLP=5).
        const float4* rp = (const float4*)(setSrc + tid * 20);
        float ov = othSrc[tid * 20 + z0];          // other mask at own cell
        #pragma unroll
        for (int q = 0; q < 5; q++) {
            float4 v = rp[q];
            // jnp.round == round-half-even == rintf
            rowbits |= (rintf(v.x) != 0.0f ? 1u : 0u) << (q * 4 + 0);
            rowbits |= (rintf(v.y) != 0.0f ? 1u : 0u) << (q * 4 + 1);
            rowbits |= (rintf(v.z) != 0.0f ? 1u : 0u) << (q * 4 + 2);
            rowbits |= (rintf(v.w) != 0.0f ? 1u : 0u) << (q * 4 + 3);
        }
        // z-pass at fixed z0: nearest set bit in own row, O(1).
        int dist = 100;
        unsigned lo = rowbits & ((2u << z0) - 1u);
        if (lo) dist = z0 - (31 - __clz(lo));
        unsigned hi = rowbits >> z0;
        if (hi) dist = min(dist, __ffs(hi) - 1);
        F1[tid] = (dist <= 19) ? dist * dist : INF_S;

        int s = (rowbits >> z0) & 1;
        oo = (rintf(ov) != 0.0f) & (s ^ 1);        // "other-only" point
    }
    // anyA: every block of this transform sees the FULL set mask via rowbits,
    // so all compute the same value; only one block will publish it.
    int anyW = __any_sync(0xffffffffu, rowbits != 0);
    if ((tid & 31) == 0 && anyW) sany = 1;         // benign race
    __syncthreads();

    // ---- y-pass: F2(x,y) = min_yp F1(x,yp) + (y-yp)^2 ----
    if (tid < 400) {
        int c[20];
        int base = x * 20;
        #pragma unroll
        for (int yp = 0; yp < 20; yp++) {
            int dy = y - yp;
            c[yp] = F1[base + yp] + dy * dy;
        }
        #pragma unroll
        for (int st = 1; st < 20; st <<= 1)
            #pragma unroll
            for (int i = 0; i + st < 20; i += (st << 1)) c[i] = min(c[i], c[i + st]);
        F2[tid] = c[0];
    }
    __syncthreads();

    // ---- x-pass + classification ----
    int enc = 0;                                   // best+1 encoded; 0 = none
    if (tid < 400) {
        int c[20];
        #pragma unroll
        for (int xp = 0; xp < 20; xp++) {
            int dx = x - xp;
            c[xp] = F2[xp * 20 + y] + dx * dx;
        }
        #pragma unroll
        for (int st = 1; st < 20; st <<= 1)
            #pragma unroll
            for (int i = 0; i + st < 20; i += (st << 1)) c[i] = min(c[i], c[i + st]);
        if (oo) enc = c[0] + 1;
    }
    enc = __reduce_max_sync(0xffffffffu, enc);
    if ((tid & 31) == 0 && enc) atomicMax(&sred, enc);
    __syncthreads();

    // ---- tail: two-level arrival tree ----
    if (tid == 0) {
        if (sred) atomicMax(&g_gmax[t * PAD], (unsigned)sred);
        if (m == 0 && z0 == 0)                      // single writer per sample
            *(volatile unsigned*)&g_any[n * PAD] = (unsigned)sany;
        __threadfence();
        unsigned c = atomicAdd(&g_cnt[t * PAD], 1); // 20 arrivals, 4 parallel addrs
        if (c == 19) {
            unsigned done = atomicAdd(&g_done, 1);  // 4 arrivals
            if (done == 3) {
                __threadfence();
                volatile unsigned* vmax = (volatile unsigned*)g_gmax;
                volatile unsigned* vany = (volatile unsigned*)g_any;
                volatile unsigned* vcnt = (volatile unsigned*)g_cnt;
                float sum = 0.0f;
                #pragma unroll
                for (int nn = 0; nn < 2; nn++) {
                    int a2   = (int)vmax[(nn * 2 + 1) * PAD] - 1; // A-only->B (set=B)
                    int b2   = (int)vmax[(nn * 2 + 0) * PAD] - 1; // B-only->A (set=A)
                    int anyA = (int)vany[nn * PAD];
                    float dA = 0.0f;
                    if (a2 >= 0) dA = (a2 > 1083) ? 1e9f : sqrtf((float)a2) * 0.05f;
                    float dB = 0.0f;
                    if (b2 >= 0) dB = anyA ? ((b2 > 1083) ? 1e9f : sqrtf((float)b2) * 0.05f)
                                           : 999.0f;
                    sum += fmaxf(dA, dB);
                    vmax[(nn * 2 + 0) * PAD] = 0;
                    vmax[(nn * 2 + 1) * PAD] = 0;
                    vany[nn * PAD] = 0;
                }
                out[0] = sum * 0.5f;
                #pragma unroll
                for (int tt = 0; tt < 4; tt++) vcnt[tt * PAD] = 0;
                *(volatile unsigned*)&g_done = 0;   // restore static-init state
            }
        }
    }
}

extern "C" void kernel_launch(void* const* d_in, const int* in_sizes, int n_in,
                              void* d_out, int out_size)
{
    const float* predict = (const float*)d_in[0];
    const float* targetp = (const float*)d_in[1];
    haus_plane<<<80, 416>>>(predict, targetp, (float*)d_out);
}